// round 3
// baseline (speedup 1.0000x reference)
#include <cuda_runtime.h>
#include <cstdint>
#include <cfloat>

// Problem constants (fixed by the reference)
#define NB   8192
#define EMB  768
#define NP   96
#define NK   256
#define ND   8
#define NKP  (NK / 2)        // 128 k-pair steps

#define NCHUNK   16          // chunks of 16 codes
#define SPC      8           // pair-steps per chunk

#define THREADS      128
#define ROWS_PER_T   4
#define ROWS_PER_BLK (THREADS * ROWS_PER_T)   // 512
#define GRID_X       (NB / ROWS_PER_BLK)      // 16

#define PAIR_STRIDE  10      // u64 per k-pair record (8 dims + c2 + pad)

typedef unsigned long long u64;

__device__ __forceinline__ u64 ffma2(u64 a, u64 b, u64 c) {
    u64 d;
    asm("fma.rn.f32x2 %0, %1, %2, %3;" : "=l"(d) : "l"(a), "l"(b), "l"(c));
    return d;
}
__device__ __forceinline__ u64 pack2(float lo, float hi) {
    u64 r;
    asm("mov.b64 %0, {%1, %2};" : "=l"(r) : "f"(lo), "f"(hi));
    return r;
}
__device__ __forceinline__ void unpack2(u64 v, float& lo, float& hi) {
    asm("mov.b64 {%0, %1}, %2;" : "=f"(lo), "=f"(hi) : "l"(v));
}

// The exact score sequence — used identically in pass 1 and pass 2 so the
// recomputation is bit-identical (the acc chain is serially dependent, so
// the compiler cannot reorder the FFMA2s).
__device__ __forceinline__ u64 score_pair(u64 c2, ulonglong2 q0, ulonglong2 q1,
                                          ulonglong2 q2, ulonglong2 q3,
                                          const u64* vd) {
    u64 acc = c2;
    acc = ffma2(vd[0], q0.x, acc);
    acc = ffma2(vd[1], q0.y, acc);
    acc = ffma2(vd[2], q1.x, acc);
    acc = ffma2(vd[3], q1.y, acc);
    acc = ffma2(vd[4], q2.x, acc);
    acc = ffma2(vd[5], q2.y, acc);
    acc = ffma2(vd[6], q3.x, acc);
    acc = ffma2(vd[7], q3.y, acc);
    return acc;
}

__global__ __launch_bounds__(THREADS, 4)
void pq_argmin_kernel(const float* __restrict__ vecs,
                      const float* __restrict__ codebook,
                      float* __restrict__ out) {
    // Per k-pair record: d0..d7 packed as (-2*c_{2s,d}, -2*c_{2s+1,d}),
    // then (||c_2s||^2, ||c_2s+1||^2). Stride 10 u64 = 80B.
    __shared__ __align__(16) u64 s_pair[NKP][PAIR_STRIDE];  // 10 KB

    const int p   = blockIdx.y;
    const int tid = threadIdx.x;

    // ---- stage codebook[p] into smem: one k-pair per thread ----
    {
        const int kp = tid;  // THREADS == NKP
        const float4* cb = reinterpret_cast<const float4*>(
            codebook + ((size_t)p * NK + 2 * kp) * ND);
        float4 a0 = cb[0], a1 = cb[1];   // code 2kp
        float4 b0 = cb[2], b1 = cb[3];   // code 2kp+1
        float c2a = a0.x*a0.x + a0.y*a0.y + a0.z*a0.z + a0.w*a0.w
                  + a1.x*a1.x + a1.y*a1.y + a1.z*a1.z + a1.w*a1.w;
        float c2b = b0.x*b0.x + b0.y*b0.y + b0.z*b0.z + b0.w*b0.w
                  + b1.x*b1.x + b1.y*b1.y + b1.z*b1.z + b1.w*b1.w;
        u64* rec = s_pair[kp];
        rec[0] = pack2(-2.f*a0.x, -2.f*b0.x);
        rec[1] = pack2(-2.f*a0.y, -2.f*b0.y);
        rec[2] = pack2(-2.f*a0.z, -2.f*b0.z);
        rec[3] = pack2(-2.f*a0.w, -2.f*b0.w);
        rec[4] = pack2(-2.f*a1.x, -2.f*b1.x);
        rec[5] = pack2(-2.f*a1.y, -2.f*b1.y);
        rec[6] = pack2(-2.f*a1.z, -2.f*b1.z);
        rec[7] = pack2(-2.f*a1.w, -2.f*b1.w);
        rec[8] = pack2(c2a, c2b);
    }
    __syncthreads();

    // ---- load 4 rows' v-slices (each slice is one 32B sector) ----
    const int rowBase = blockIdx.x * ROWS_PER_BLK;
    int rows[ROWS_PER_T];
    rows[0] = rowBase + tid;
    rows[1] = rows[0] + THREADS;
    rows[2] = rows[0] + 2 * THREADS;
    rows[3] = rows[0] + 3 * THREADS;

    // v duplicated into both f32x2 lanes, per row per dim
    u64 vd[ROWS_PER_T][ND];
#pragma unroll
    for (int r = 0; r < ROWS_PER_T; r++) {
        const float4* g = reinterpret_cast<const float4*>(
            vecs + (size_t)rows[r] * EMB + p * ND);
        float4 a = g[0], b = g[1];
        vd[r][0] = pack2(a.x, a.x);
        vd[r][1] = pack2(a.y, a.y);
        vd[r][2] = pack2(a.z, a.z);
        vd[r][3] = pack2(a.w, a.w);
        vd[r][4] = pack2(b.x, b.x);
        vd[r][5] = pack2(b.y, b.y);
        vd[r][6] = pack2(b.z, b.z);
        vd[r][7] = pack2(b.w, b.w);
    }

    float gbest[ROWS_PER_T] = {FLT_MAX, FLT_MAX, FLT_MAX, FLT_MAX};
    int   cid  [ROWS_PER_T] = {0, 0, 0, 0};

    // ---- pass 1: chunked min-value scan (FMNMX-only inner loop) ----
    for (int c = 0; c < NCHUNK; c++) {
        float cm0[ROWS_PER_T], cm1[ROWS_PER_T];
#pragma unroll
        for (int r = 0; r < ROWS_PER_T; r++) { cm0[r] = FLT_MAX; cm1[r] = FLT_MAX; }

#pragma unroll
        for (int s = 0; s < SPC; s++) {
            const u64* rec = s_pair[c * SPC + s];
            const ulonglong2* rp = reinterpret_cast<const ulonglong2*>(rec);
            ulonglong2 q0 = rp[0];
            ulonglong2 q1 = rp[1];
            ulonglong2 q2 = rp[2];
            ulonglong2 q3 = rp[3];
            u64 c2p = rec[8];

#pragma unroll
            for (int r = 0; r < ROWS_PER_T; r++) {
                u64 acc = score_pair(c2p, q0, q1, q2, q3, vd[r]);
                float sa, sb;
                unpack2(acc, sa, sb);
                cm0[r] = fminf(cm0[r], sa);   // even-k stream (independent chain)
                cm1[r] = fminf(cm1[r], sb);   // odd-k stream
            }
        }

#pragma unroll
        for (int r = 0; r < ROWS_PER_T; r++) {
            float m = fminf(cm0[r], cm1[r]);
            // strict '<': earlier chunk wins exact ties
            if (m < gbest[r]) { gbest[r] = m; cid[r] = c; }
        }
    }

    // ---- pass 2: recover index within winning chunk (bit-exact recompute) ----
    int idx[ROWS_PER_T] = {0, 0, 0, 0};
#pragma unroll
    for (int r = 0; r < ROWS_PER_T; r++) {
        const int base = cid[r] * SPC;
        // descending overwrite => final idx is the LOWEST matching k
#pragma unroll
        for (int s = SPC - 1; s >= 0; s--) {
            const u64* rec = s_pair[base + s];
            const ulonglong2* rp = reinterpret_cast<const ulonglong2*>(rec);
            ulonglong2 q0 = rp[0];
            ulonglong2 q1 = rp[1];
            ulonglong2 q2 = rp[2];
            ulonglong2 q3 = rp[3];
            u64 c2p = rec[8];
            u64 acc = score_pair(c2p, q0, q1, q2, q3, vd[r]);
            float sa, sb;
            unpack2(acc, sa, sb);
            if (sb == gbest[r]) idx[r] = 2 * (base + s) + 1;
            if (sa == gbest[r]) idx[r] = 2 * (base + s);
        }
    }

    // ---- epilogue: gather winning code; c = (-2c) * -0.5 is bit-exact ----
#pragma unroll
    for (int r = 0; r < ROWS_PER_T; r++) {
        int k = idx[r];
        const float* h = reinterpret_cast<const float*>(s_pair[k >> 1]) + (k & 1);
        float4 oa, ob;
        oa.x = -0.5f * h[0];
        oa.y = -0.5f * h[2];
        oa.z = -0.5f * h[4];
        oa.w = -0.5f * h[6];
        ob.x = -0.5f * h[8];
        ob.y = -0.5f * h[10];
        ob.z = -0.5f * h[12];
        ob.w = -0.5f * h[14];
        float4* o = reinterpret_cast<float4*>(out + (size_t)rows[r] * EMB + p * ND);
        o[0] = oa;
        o[1] = ob;
    }
}

extern "C" void kernel_launch(void* const* d_in, const int* in_sizes, int n_in,
                              void* d_out, int out_size) {
    const float* vecs     = (const float*)d_in[0];   // [8192, 768] f32
    const float* codebook = (const float*)d_in[1];   // [96, 256, 8] f32
    float* out            = (float*)d_out;           // [8192, 768] f32

    dim3 grid(GRID_X, NP);
    dim3 block(THREADS);
    pq_argmin_kernel<<<grid, block>>>(vecs, codebook, out);
}

// round 4
// speedup vs baseline: 1.9053x; 1.9053x over previous
#include <cuda_runtime.h>
#include <cstdint>
#include <cfloat>

// Problem constants (fixed by the reference)
#define NB   8192
#define EMB  768
#define NP   96
#define NK   256
#define ND   8
#define NKP  (NK / 2)        // 128 k-pair steps

#define THREADS      128
#define ROWS_PER_T   4
#define ROWS_PER_BLK (THREADS * ROWS_PER_T)   // 512
#define GRID_X       (NB / ROWS_PER_BLK)      // 16

#define PAIR_STRIDE  10      // u64 per k-pair record (8 dims + c2 + pad)

typedef unsigned long long u64;

__device__ __forceinline__ u64 ffma2(u64 a, u64 b, u64 c) {
    u64 d;
    asm("fma.rn.f32x2 %0, %1, %2, %3;" : "=l"(d) : "l"(a), "l"(b), "l"(c));
    return d;
}
__device__ __forceinline__ u64 pack2(float lo, float hi) {
    u64 r;
    asm("mov.b64 %0, {%1, %2};" : "=l"(r) : "f"(lo), "f"(hi));
    return r;
}
__device__ __forceinline__ void unpack2(u64 v, float& lo, float& hi) {
    asm("mov.b64 {%0, %1}, %2;" : "=f"(lo), "=f"(hi) : "l"(v));
}

// Exact score chain — serially dependent, so recomputation is bit-identical.
__device__ __forceinline__ u64 score_pair(u64 c2, ulonglong2 q0, ulonglong2 q1,
                                          ulonglong2 q2, ulonglong2 q3,
                                          const u64* vd) {
    u64 acc = c2;
    acc = ffma2(vd[0], q0.x, acc);
    acc = ffma2(vd[1], q0.y, acc);
    acc = ffma2(vd[2], q1.x, acc);
    acc = ffma2(vd[3], q1.y, acc);
    acc = ffma2(vd[4], q2.x, acc);
    acc = ffma2(vd[5], q2.y, acc);
    acc = ffma2(vd[6], q3.x, acc);
    acc = ffma2(vd[7], q3.y, acc);
    return acc;
}

__global__ __launch_bounds__(THREADS, 6)
void pq_argmin_kernel(const float* __restrict__ vecs,
                      const float* __restrict__ codebook,
                      float* __restrict__ out) {
    // Per k-pair record: d0..d7 packed as (-2*c_{2s,d}, -2*c_{2s+1,d}),
    // then (||c_2s||^2, ||c_2s+1||^2). Stride 10 u64 = 80B.
    __shared__ __align__(16) u64 s_pair[NKP][PAIR_STRIDE];  // 10 KB

    const int p   = blockIdx.y;
    const int tid = threadIdx.x;

    // ---- stage codebook[p] into smem: one k-pair per thread ----
    {
        const int kp = tid;  // THREADS == NKP
        const float4* cb = reinterpret_cast<const float4*>(
            codebook + ((size_t)p * NK + 2 * kp) * ND);
        float4 a0 = cb[0], a1 = cb[1];   // code 2kp
        float4 b0 = cb[2], b1 = cb[3];   // code 2kp+1
        float c2a = a0.x*a0.x + a0.y*a0.y + a0.z*a0.z + a0.w*a0.w
                  + a1.x*a1.x + a1.y*a1.y + a1.z*a1.z + a1.w*a1.w;
        float c2b = b0.x*b0.x + b0.y*b0.y + b0.z*b0.z + b0.w*b0.w
                  + b1.x*b1.x + b1.y*b1.y + b1.z*b1.z + b1.w*b1.w;
        u64* rec = s_pair[kp];
        rec[0] = pack2(-2.f*a0.x, -2.f*b0.x);
        rec[1] = pack2(-2.f*a0.y, -2.f*b0.y);
        rec[2] = pack2(-2.f*a0.z, -2.f*b0.z);
        rec[3] = pack2(-2.f*a0.w, -2.f*b0.w);
        rec[4] = pack2(-2.f*a1.x, -2.f*b1.x);
        rec[5] = pack2(-2.f*a1.y, -2.f*b1.y);
        rec[6] = pack2(-2.f*a1.z, -2.f*b1.z);
        rec[7] = pack2(-2.f*a1.w, -2.f*b1.w);
        rec[8] = pack2(c2a, c2b);
    }
    __syncthreads();

    // ---- load 4 rows' v-slices (each slice is one 32B sector) ----
    const int rowBase = blockIdx.x * ROWS_PER_BLK;
    int rows[ROWS_PER_T];
    rows[0] = rowBase + tid;
    rows[1] = rows[0] + THREADS;
    rows[2] = rows[0] + 2 * THREADS;
    rows[3] = rows[0] + 3 * THREADS;

    // v duplicated into both f32x2 lanes, per row per dim
    u64 vd[ROWS_PER_T][ND];
#pragma unroll
    for (int r = 0; r < ROWS_PER_T; r++) {
        const float4* g = reinterpret_cast<const float4*>(
            vecs + (size_t)rows[r] * EMB + p * ND);
        float4 a = g[0], b = g[1];
        vd[r][0] = pack2(a.x, a.x);
        vd[r][1] = pack2(a.y, a.y);
        vd[r][2] = pack2(a.z, a.z);
        vd[r][3] = pack2(a.w, a.w);
        vd[r][4] = pack2(b.x, b.x);
        vd[r][5] = pack2(b.y, b.y);
        vd[r][6] = pack2(b.z, b.z);
        vd[r][7] = pack2(b.w, b.w);
    }

    float best    [ROWS_PER_T] = {FLT_MAX, FLT_MAX, FLT_MAX, FLT_MAX};
    int   bestStep[ROWS_PER_T] = {0, 0, 0, 0};

    // ---- main loop: 128 pair-steps, minimal bookkeeping ----
#pragma unroll 2
    for (int s = 0; s < NKP; s++) {
        const u64* rec = s_pair[s];
        const ulonglong2* rp = reinterpret_cast<const ulonglong2*>(rec);
        ulonglong2 q0 = rp[0];   // dims 0,1
        ulonglong2 q1 = rp[1];   // dims 2,3
        ulonglong2 q2 = rp[2];   // dims 4,5
        ulonglong2 q3 = rp[3];   // dims 6,7
        u64 c2p = rec[8];

#pragma unroll
        for (int r = 0; r < ROWS_PER_T; r++) {
            u64 acc = score_pair(c2p, q0, q1, q2, q3, vd[r]);
            float sa, sb;
            unpack2(acc, sa, sb);
            float m = fminf(sa, sb);
            // strict '<': earliest step wins exact ties
            if (m < best[r]) bestStep[r] = s;
            best[r] = fminf(best[r], m);
        }
    }

    // ---- resolve even/odd within winning step (bit-exact recompute) ----
    int idx[ROWS_PER_T];
#pragma unroll
    for (int r = 0; r < ROWS_PER_T; r++) {
        const int s = bestStep[r];
        const u64* rec = s_pair[s];
        const ulonglong2* rp = reinterpret_cast<const ulonglong2*>(rec);
        u64 acc = score_pair(rec[8], rp[0], rp[1], rp[2], rp[3], vd[r]);
        float sa, sb;
        unpack2(acc, sa, sb);
        // sa == best  -> even (lower) k wins, matching jnp.argmax tie rule
        idx[r] = 2 * s + ((sa == best[r]) ? 0 : 1);
    }

    // ---- epilogue: gather winning code; c = (-2c) * -0.5 is bit-exact ----
#pragma unroll
    for (int r = 0; r < ROWS_PER_T; r++) {
        int k = idx[r];
        const float* h = reinterpret_cast<const float*>(s_pair[k >> 1]) + (k & 1);
        float4 oa, ob;
        oa.x = -0.5f * h[0];
        oa.y = -0.5f * h[2];
        oa.z = -0.5f * h[4];
        oa.w = -0.5f * h[6];
        ob.x = -0.5f * h[8];
        ob.y = -0.5f * h[10];
        ob.z = -0.5f * h[12];
        ob.w = -0.5f * h[14];
        float4* o = reinterpret_cast<float4*>(out + (size_t)rows[r] * EMB + p * ND);
        o[0] = oa;
        o[1] = ob;
    }
}

extern "C" void kernel_launch(void* const* d_in, const int* in_sizes, int n_in,
                              void* d_out, int out_size) {
    const float* vecs     = (const float*)d_in[0];   // [8192, 768] f32
    const float* codebook = (const float*)d_in[1];   // [96, 256, 8] f32
    float* out            = (float*)d_out;           // [8192, 768] f32

    dim3 grid(GRID_X, NP);
    dim3 block(THREADS);
    pq_argmin_kernel<<<grid, block>>>(vecs, codebook, out);
}